// round 8
// baseline (speedup 1.0000x reference)
#include <cuda_runtime.h>
#include <cuda_bf16.h>
#include <cstdint>

// LinearQuant: q = clip(floor(x*16 + 0.5), -128, 127) / 16.  HBM-bound stream.
// R8: persistent kernel, CONTIGUOUS per-CTA chunks. All block-interleaved
// variants pinned at ~6.13 TB/s; this changes the DRAM-side pattern to
// ~1184 long sequential streams (one per CTA, ~350KB each) for better
// row-buffer locality / fewer read-write turnarounds per bank.

__device__ __forceinline__ float quant1(float x) {
    float q = floorf(fmaf(x, 16.0f, 0.5f));
    q = fminf(fmaxf(q, -128.0f), 127.0f);
    return q * 0.0625f;
}

__device__ __forceinline__ void ld_v8_cs(const float* p, float r[8]) {
    asm volatile(
        "ld.global.cs.v8.f32 {%0,%1,%2,%3,%4,%5,%6,%7}, [%8];"
        : "=f"(r[0]), "=f"(r[1]), "=f"(r[2]), "=f"(r[3]),
          "=f"(r[4]), "=f"(r[5]), "=f"(r[6]), "=f"(r[7])
        : "l"(p));
}

__device__ __forceinline__ void st_v8_cs(float* p, const float r[8]) {
    asm volatile(
        "st.global.cs.v8.f32 [%0], {%1,%2,%3,%4,%5,%6,%7,%8};"
        :: "l"(p),
           "f"(r[0]), "f"(r[1]), "f"(r[2]), "f"(r[3]),
           "f"(r[4]), "f"(r[5]), "f"(r[6]), "f"(r[7])
        : "memory");
}

#define THREADS 256
#define GRID 1184  // 148 SMs x 8 CTAs

__global__ void __launch_bounds__(THREADS) linquant_chunk_kernel(
    const float* __restrict__ in, float* __restrict__ out, int n8)
{
    // Contiguous chunk per CTA, in units of 8 floats (32B).
    int chunk = (n8 + GRID - 1) / GRID;
    int begin = blockIdx.x * chunk;
    int end   = begin + chunk;
    if (end > n8) end = n8;

    int i = begin + threadIdx.x;

    // Unroll-by-2 main loop (front-batched pair of 256-bit loads).
    for (; i + THREADS < end; i += 2 * THREADS) {
        float a[8], b[8];
        ld_v8_cs(in + (size_t)i * 8, a);
        ld_v8_cs(in + (size_t)(i + THREADS) * 8, b);
        #pragma unroll
        for (int j = 0; j < 8; j++) a[j] = quant1(a[j]);
        #pragma unroll
        for (int j = 0; j < 8; j++) b[j] = quant1(b[j]);
        st_v8_cs(out + (size_t)i * 8, a);
        st_v8_cs(out + (size_t)(i + THREADS) * 8, b);
    }
    if (i < end) {
        float a[8];
        ld_v8_cs(in + (size_t)i * 8, a);
        #pragma unroll
        for (int j = 0; j < 8; j++) a[j] = quant1(a[j]);
        st_v8_cs(out + (size_t)i * 8, a);
    }
}

__global__ void __launch_bounds__(256) linquant_tail_kernel(
    const float* __restrict__ in, float* __restrict__ out, int start, int n)
{
    int i = start + blockIdx.x * blockDim.x + threadIdx.x;
    if (i < n) {
        out[i] = quant1(in[i]);
    }
}

extern "C" void kernel_launch(void* const* d_in, const int* in_sizes, int n_in,
                              void* d_out, int out_size) {
    const float* in = (const float*)d_in[0];
    float* out = (float*)d_out;
    int n = in_sizes[0];

    int n8 = n / 8;
    if (n8 > 0) {
        linquant_chunk_kernel<<<GRID, THREADS>>>(in, out, n8);
    }
    int rem = n - n8 * 8;
    if (rem > 0) {
        linquant_tail_kernel<<<1, 256>>>(in, out, n8 * 8, n);
    }
}

// round 9
// speedup vs baseline: 1.1000x; 1.1000x over previous
#include <cuda_runtime.h>
#include <cuda_bf16.h>
#include <cstdint>

// LinearQuant: q = clip(floor(x*16 + 0.5), -128, 127) / 16.  HBM-bound stream.
// FINAL (R9 = best-measured R3 chassis): 256-bit streaming ld/st (.cs),
// 4x 32B per thread front-batched, block-interleaved addressing.
//
// Convergence evidence across R1-R8: occ 30-79%, 16-256B/thread, 128/256-bit,
// evict_last/evict_first/cs policies, interleaved vs contiguous chunks -- all
// interleaved variants pin at 6.11-6.16 TB/s (the part's mixed 1R:1W DRAM
// ceiling, ~77% of 8TB/s spec); L2-residency hints are inert cross-launch on
// this part; contiguous chunking regresses (LTS imbalance). This config
// measured fastest: 65.54us dur / 57.8us kernel.

__device__ __forceinline__ float quant1(float x) {
    float q = floorf(fmaf(x, 16.0f, 0.5f));
    q = fminf(fmaxf(q, -128.0f), 127.0f);
    return q * 0.0625f;
}

__device__ __forceinline__ void ld_v8_cs(const float* p, float r[8]) {
    asm volatile(
        "ld.global.cs.v8.f32 {%0,%1,%2,%3,%4,%5,%6,%7}, [%8];"
        : "=f"(r[0]), "=f"(r[1]), "=f"(r[2]), "=f"(r[3]),
          "=f"(r[4]), "=f"(r[5]), "=f"(r[6]), "=f"(r[7])
        : "l"(p));
}

__device__ __forceinline__ void st_v8_cs(float* p, const float r[8]) {
    asm volatile(
        "st.global.cs.v8.f32 [%0], {%1,%2,%3,%4,%5,%6,%7,%8};"
        :: "l"(p),
           "f"(r[0]), "f"(r[1]), "f"(r[2]), "f"(r[3]),
           "f"(r[4]), "f"(r[5]), "f"(r[6]), "f"(r[7])
        : "memory");
}

#define VPT 4  // 32B chunks per thread (128B/thread total)

__global__ void __launch_bounds__(256) linquant_v8_kernel(
    const float* __restrict__ in, float* __restrict__ out, int n8)
{
    // index in units of 8 floats (32B)
    int base = blockIdx.x * (blockDim.x * VPT) + threadIdx.x;

    if (base + 3 * blockDim.x < n8) {
        float v0[8], v1[8], v2[8], v3[8];
        ld_v8_cs(in + (size_t)(base + 0 * blockDim.x) * 8, v0);
        ld_v8_cs(in + (size_t)(base + 1 * blockDim.x) * 8, v1);
        ld_v8_cs(in + (size_t)(base + 2 * blockDim.x) * 8, v2);
        ld_v8_cs(in + (size_t)(base + 3 * blockDim.x) * 8, v3);
        #pragma unroll
        for (int j = 0; j < 8; j++) v0[j] = quant1(v0[j]);
        #pragma unroll
        for (int j = 0; j < 8; j++) v1[j] = quant1(v1[j]);
        #pragma unroll
        for (int j = 0; j < 8; j++) v2[j] = quant1(v2[j]);
        #pragma unroll
        for (int j = 0; j < 8; j++) v3[j] = quant1(v3[j]);
        st_v8_cs(out + (size_t)(base + 0 * blockDim.x) * 8, v0);
        st_v8_cs(out + (size_t)(base + 1 * blockDim.x) * 8, v1);
        st_v8_cs(out + (size_t)(base + 2 * blockDim.x) * 8, v2);
        st_v8_cs(out + (size_t)(base + 3 * blockDim.x) * 8, v3);
    } else {
        #pragma unroll
        for (int k = 0; k < VPT; k++) {
            int i8 = base + k * blockDim.x;
            if (i8 < n8) {
                float v[8];
                ld_v8_cs(in + (size_t)i8 * 8, v);
                #pragma unroll
                for (int j = 0; j < 8; j++) v[j] = quant1(v[j]);
                st_v8_cs(out + (size_t)i8 * 8, v);
            }
        }
    }
}

__global__ void __launch_bounds__(256) linquant_tail_kernel(
    const float* __restrict__ in, float* __restrict__ out, int start, int n)
{
    int i = start + blockIdx.x * blockDim.x + threadIdx.x;
    if (i < n) {
        out[i] = quant1(in[i]);
    }
}

extern "C" void kernel_launch(void* const* d_in, const int* in_sizes, int n_in,
                              void* d_out, int out_size) {
    const float* in = (const float*)d_in[0];
    float* out = (float*)d_out;
    int n = in_sizes[0];

    int n8 = n / 8;
    if (n8 > 0) {
        const int threads = 256;
        const int per_block = threads * VPT;  // in 8-float units
        int blocks = (n8 + per_block - 1) / per_block;
        linquant_v8_kernel<<<blocks, threads>>>(in, out, n8);
    }
    int rem = n - n8 * 8;
    if (rem > 0) {
        linquant_tail_kernel<<<1, 256>>>(in, out, n8 * 8, n);
    }
}

// round 10
// speedup vs baseline: 1.1016x; 1.0015x over previous
#include <cuda_runtime.h>
#include <cuda_bf16.h>
#include <cstdint>

// LinearQuant: q = clip(floor(x*16 + 0.5), -128, 127) / 16.  HBM-bound stream.
// R10: final micro-probe. 256-bit .cs streaming ld/st, VPT=2 (64B/thread) ->
// ~2x occupancy vs VPT=4 at identical interleave. Session evidence: all
// interleaved variants pin at the 6.13-6.16 TB/s mixed 1R:1W DRAM ceiling;
// highest reading came from the highest-occupancy variant, so trade MLP for
// warps. Expected within noise of 65.5us best.

__device__ __forceinline__ float quant1(float x) {
    float q = floorf(fmaf(x, 16.0f, 0.5f));
    q = fminf(fmaxf(q, -128.0f), 127.0f);
    return q * 0.0625f;
}

__device__ __forceinline__ void ld_v8_cs(const float* p, float r[8]) {
    asm volatile(
        "ld.global.cs.v8.f32 {%0,%1,%2,%3,%4,%5,%6,%7}, [%8];"
        : "=f"(r[0]), "=f"(r[1]), "=f"(r[2]), "=f"(r[3]),
          "=f"(r[4]), "=f"(r[5]), "=f"(r[6]), "=f"(r[7])
        : "l"(p));
}

__device__ __forceinline__ void st_v8_cs(float* p, const float r[8]) {
    asm volatile(
        "st.global.cs.v8.f32 [%0], {%1,%2,%3,%4,%5,%6,%7,%8};"
        :: "l"(p),
           "f"(r[0]), "f"(r[1]), "f"(r[2]), "f"(r[3]),
           "f"(r[4]), "f"(r[5]), "f"(r[6]), "f"(r[7])
        : "memory");
}

#define VPT 2  // 32B chunks per thread (64B/thread total)

__global__ void __launch_bounds__(256) linquant_v8x2_kernel(
    const float* __restrict__ in, float* __restrict__ out, int n8)
{
    // index in units of 8 floats (32B)
    int base = blockIdx.x * (blockDim.x * VPT) + threadIdx.x;

    if (base + blockDim.x < n8) {
        float v0[8], v1[8];
        ld_v8_cs(in + (size_t)(base + 0 * blockDim.x) * 8, v0);
        ld_v8_cs(in + (size_t)(base + 1 * blockDim.x) * 8, v1);
        #pragma unroll
        for (int j = 0; j < 8; j++) v0[j] = quant1(v0[j]);
        #pragma unroll
        for (int j = 0; j < 8; j++) v1[j] = quant1(v1[j]);
        st_v8_cs(out + (size_t)(base + 0 * blockDim.x) * 8, v0);
        st_v8_cs(out + (size_t)(base + 1 * blockDim.x) * 8, v1);
    } else {
        #pragma unroll
        for (int k = 0; k < VPT; k++) {
            int i8 = base + k * blockDim.x;
            if (i8 < n8) {
                float v[8];
                ld_v8_cs(in + (size_t)i8 * 8, v);
                #pragma unroll
                for (int j = 0; j < 8; j++) v[j] = quant1(v[j]);
                st_v8_cs(out + (size_t)i8 * 8, v);
            }
        }
    }
}

__global__ void __launch_bounds__(256) linquant_tail_kernel(
    const float* __restrict__ in, float* __restrict__ out, int start, int n)
{
    int i = start + blockIdx.x * blockDim.x + threadIdx.x;
    if (i < n) {
        out[i] = quant1(in[i]);
    }
}

extern "C" void kernel_launch(void* const* d_in, const int* in_sizes, int n_in,
                              void* d_out, int out_size) {
    const float* in = (const float*)d_in[0];
    float* out = (float*)d_out;
    int n = in_sizes[0];

    int n8 = n / 8;
    if (n8 > 0) {
        const int threads = 256;
        const int per_block = threads * VPT;  // in 8-float units
        int blocks = (n8 + per_block - 1) / per_block;
        linquant_v8x2_kernel<<<blocks, threads>>>(in, out, n8);
    }
    int rem = n - n8 * 8;
    if (rem > 0) {
        linquant_tail_kernel<<<1, 256>>>(in, out, n8 * 8, n);
    }
}